// round 14
// baseline (speedup 1.0000x reference)
#include <cuda_runtime.h>
#include <cuda_fp16.h>
#include <mma.h>
#include <cstdint>
#include <cstddef>

using namespace nvcuda;

#define B_ 64
#define S_ 2048
#define E_ 512
#define C_ 512
#define H_ 256

// ---------------- scratch (static device globals; no allocation) ----------------
__device__ float g_ctx[B_ * H_];         // ctx_feat + b_ctx + b_word  [B,H]
__device__ float g_scores[B_ * S_];      // pre-softmax scores         [B,S]
__device__ float g_attn[B_ * S_];        // normalized attention       [B,S]
__device__ float g_part[32 * B_ * E_];   // weighted-sum partials      [32,B,E]

// ---------------------------------------------------------------------------
// Kernel 1: ctx_feat[b,h] = b_ctx[h] + b_word[h] + context[b,:] . W_ctx[h,:]
// ---------------------------------------------------------------------------
__global__ void ctx_kernel(const float* __restrict__ context,
                           const float* __restrict__ W_ctx,
                           const float* __restrict__ b_ctx,
                           const float* __restrict__ b_word) {
    int b = blockIdx.x, h = threadIdx.x;
    const float4* wr = reinterpret_cast<const float4*>(W_ctx + (size_t)h * C_);
    const float4* cr = reinterpret_cast<const float4*>(context + (size_t)b * C_);
    float acc = b_ctx[h] + b_word[h];
#pragma unroll 8
    for (int i = 0; i < C_ / 4; i++) {
        float4 w = wr[i];
        float4 c = cr[i];
        acc += w.x * c.x + w.y * c.y + w.z * c.z + w.w * c.w;
    }
    g_ctx[b * H_ + h] = acc;
}

// ---------------------------------------------------------------------------
// Kernel 2: scores = w_hidden . tanh(A@W_word^T + ctx), fp16 wmma m16n16k16.
// fp16 RN has the same 10-bit mantissa as tf32 but K=16/instr vs K=8 -> half
// the HMMA instructions (legacy pipe is instruction-issue bound).
// CTA = 128 s-rows x 256 H-cols x K=512, 512 threads (16 warps, wm0..3 x wn0..3).
// Register-prefetched LDG -> cvt.f16 -> STS double-buffered K=32 chunks.
// ---------------------------------------------------------------------------
#define LDH 40                 // smem leading dim in halves (80B, 16B multiple)
#define A_HL (128 * LDH)       // halves per A buffer (5120)
#define B_HL (256 * LDH)       // halves per B buffer (10240)
#define LDWF 132

__global__ __launch_bounds__(512, 1) void scores_kernel(
    const float* __restrict__ A,         // [B,S,E]
    const float* __restrict__ Ww,        // W_word [H,E]
    const int* __restrict__ lengths,
    const float* __restrict__ w_hidden) {
    int b = blockIdx.y;
    int s0 = blockIdx.x * 128;
    int len = lengths[b];
    if (s0 >= len) return;  // scores past length are never read

    extern __shared__ __align__(128) char smc[];
    __half* As0 = reinterpret_cast<__half*>(smc);             // [2][A_HL]
    __half* Bs0 = reinterpret_cast<__half*>(smc + 2 * A_HL * 2);  // [2][B_HL]
    float* epif = reinterpret_cast<float*>(smc);              // epilogue 128xLDWF
    float* ctx_s = reinterpret_cast<float*>(smc + 128 * LDWF * 4);
    float* wh_s = ctx_s + 256;

    int tid = threadIdx.x;
    int lane = tid & 31, wid = tid >> 5;
    int wm = wid & 3, wn = wid >> 2;

    if (tid < 256) {
        ctx_s[tid] = g_ctx[b * H_ + tid];
        wh_s[tid] = w_hidden[tid];
    }

    wmma::fragment<wmma::accumulator, 16, 16, 16, float> acc[2][4];
#pragma unroll
    for (int mi = 0; mi < 2; mi++)
#pragma unroll
        for (int ni = 0; ni < 4; ni++) wmma::fill_fragment(acc[mi][ni], 0.0f);

    const float* Ab = A + ((size_t)b * S_ + s0) * E_;

    // per-thread staging slots (K=32 chunk): A 2 x float4, B 4 x float4
    int ar[2], ac[2], br[4], bc[4];
#pragma unroll
    for (int i = 0; i < 2; i++) {
        int idx = tid + i * 512;
        ar[i] = idx >> 3;
        ac[i] = (idx & 7) * 4;
    }
#pragma unroll
    for (int i = 0; i < 4; i++) {
        int idx = tid + i * 512;
        br[i] = idx >> 3;
        bc[i] = (idx & 7) * 4;
    }

    float4 ra[2], rb[4];
    // prefetch chunk 0
#pragma unroll
    for (int i = 0; i < 2; i++)
        ra[i] = *reinterpret_cast<const float4*>(Ab + (size_t)ar[i] * E_ + ac[i]);
#pragma unroll
    for (int i = 0; i < 4; i++)
        rb[i] = *reinterpret_cast<const float4*>(Ww + (size_t)br[i] * E_ + bc[i]);

    for (int kc = 0; kc < 16; kc++) {
        int buf = kc & 1;
        __half* Asb = As0 + buf * A_HL;
        __half* Bsb = Bs0 + buf * B_HL;
        // convert + store chunk kc (writes buf; other warps may still mma on buf^1)
#pragma unroll
        for (int i = 0; i < 2; i++) {
            __half2 p0 = __floats2half2_rn(ra[i].x, ra[i].y);
            __half2 p1 = __floats2half2_rn(ra[i].z, ra[i].w);
            uint2 u = make_uint2(*reinterpret_cast<uint32_t*>(&p0),
                                 *reinterpret_cast<uint32_t*>(&p1));
            *reinterpret_cast<uint2*>(&Asb[ar[i] * LDH + ac[i]]) = u;
        }
#pragma unroll
        for (int i = 0; i < 4; i++) {
            __half2 p0 = __floats2half2_rn(rb[i].x, rb[i].y);
            __half2 p1 = __floats2half2_rn(rb[i].z, rb[i].w);
            uint2 u = make_uint2(*reinterpret_cast<uint32_t*>(&p0),
                                 *reinterpret_cast<uint32_t*>(&p1));
            *reinterpret_cast<uint2*>(&Bsb[br[i] * LDH + bc[i]]) = u;
        }
        __syncthreads();
        // prefetch chunk kc+1 (latency hides under the mma below)
        if (kc + 1 < 16) {
            int k0 = (kc + 1) * 32;
#pragma unroll
            for (int i = 0; i < 2; i++)
                ra[i] = *reinterpret_cast<const float4*>(Ab + (size_t)ar[i] * E_ + k0 + ac[i]);
#pragma unroll
            for (int i = 0; i < 4; i++)
                rb[i] = *reinterpret_cast<const float4*>(Ww + (size_t)br[i] * E_ + k0 + bc[i]);
        }
        const __half* As = As0 + buf * A_HL;
        const __half* Bs = Bs0 + buf * B_HL;
#pragma unroll
        for (int kk = 0; kk < 2; kk++) {
            int ko = kk * 16;
            wmma::fragment<wmma::matrix_a, 16, 16, 16, __half, wmma::row_major> af[2];
            wmma::load_matrix_sync(af[0], As + (wm * 32) * LDH + ko, LDH);
            wmma::load_matrix_sync(af[1], As + (wm * 32 + 16) * LDH + ko, LDH);
#pragma unroll
            for (int ni = 0; ni < 4; ni++) {
                wmma::fragment<wmma::matrix_b, 16, 16, 16, __half, wmma::col_major> bf;
                wmma::load_matrix_sync(bf, Bs + (wn * 64 + ni * 16) * LDH + ko, LDH);
                wmma::mma_sync(acc[0][ni], af[0], bf, acc[0][ni]);
                wmma::mma_sync(acc[1][ni], af[1], bf, acc[1][ni]);
            }
        }
        // no trailing sync: next iteration writes buf^1, which every warp already
        // finished reading before the sync above (mma(kc-1) precedes STS(kc)).
    }

    // ---- epilogue: two column-halves via smem, tanh + dot(w_hidden) ----
    float psum[8];
#pragma unroll
    for (int rr = 0; rr < 8; rr++) psum[rr] = 0.0f;

#pragma unroll
    for (int hh = 0; hh < 2; hh++) {
        __syncthreads();
        if ((wn >> 1) == hh) {
            int cw = (wn & 1) * 64;
#pragma unroll
            for (int mi = 0; mi < 2; mi++)
#pragma unroll
                for (int ni = 0; ni < 4; ni++)
                    wmma::store_matrix_sync(
                        epif + (wm * 32 + mi * 16) * LDWF + cw + ni * 16,
                        acc[mi][ni], LDWF, wmma::mem_row_major);
        }
        __syncthreads();
#pragma unroll
        for (int rr = 0; rr < 8; rr++) {
            int r = wid * 8 + rr;
#pragma unroll
            for (int j = 0; j < 4; j++) {
                int c = lane + j * 32;
                float x = epif[r * LDWF + c] + ctx_s[hh * 128 + c];
                x = fminf(fmaxf(x, -15.0f), 15.0f);
                float e2 = __expf(2.0f * x);
                psum[rr] += __fdividef(e2 - 1.0f, e2 + 1.0f) * wh_s[hh * 128 + c];
            }
        }
    }
#pragma unroll
    for (int rr = 0; rr < 8; rr++) {
        float s = psum[rr];
#pragma unroll
        for (int o = 16; o > 0; o >>= 1) s += __shfl_xor_sync(0xffffffffu, s, o);
        if (lane == 0) g_scores[(size_t)b * S_ + s0 + wid * 8 + rr] = s;
    }
}

// ---------------------------------------------------------------------------
// Kernel 3: masked softmax (exact: exp(s-m)/L on valid prefix)
// ---------------------------------------------------------------------------
__global__ __launch_bounds__(256) void attn_softmax_kernel(const int* __restrict__ lengths,
                                                           float* __restrict__ attn_out) {
    int b = blockIdx.x, tid = threadIdx.x;
    int lane = tid & 31, wid = tid >> 5;
    int len = lengths[b];
    const float* sc = g_scores + (size_t)b * S_;

    float v[8];
    float m = -1e30f;
#pragma unroll
    for (int i = 0; i < 8; i++) {
        int s = tid + i * 256;
        v[i] = (s < len) ? sc[s] : -1e30f;
        m = fmaxf(m, v[i]);
    }
#pragma unroll
    for (int o = 16; o > 0; o >>= 1) m = fmaxf(m, __shfl_xor_sync(0xffffffffu, m, o));
    __shared__ float red[8];
    if (lane == 0) red[wid] = m;
    __syncthreads();
    float mm = red[0];
#pragma unroll
    for (int i = 1; i < 8; i++) mm = fmaxf(mm, red[i]);

    float t[8];
    float L = 0.0f;
#pragma unroll
    for (int i = 0; i < 8; i++) {
        int s = tid + i * 256;
        t[i] = (s < len) ? __expf(v[i] - mm) : 0.0f;
        L += t[i];
    }
#pragma unroll
    for (int o = 16; o > 0; o >>= 1) L += __shfl_xor_sync(0xffffffffu, L, o);
    __syncthreads();
    if (lane == 0) red[wid] = L;
    __syncthreads();
    float Lt = 0.0f;
#pragma unroll
    for (int i = 0; i < 8; i++) Lt += red[i];
    float inv = __fdividef(1.0f, Lt);

#pragma unroll
    for (int i = 0; i < 8; i++) {
        int s = tid + i * 256;
        float a = t[i] * inv;
        g_attn[(size_t)b * S_ + s] = a;
        if (attn_out) attn_out[(size_t)b * S_ + s] = a;
    }
}

// ---------------------------------------------------------------------------
// Kernel 4: weighted-sum partials. grid (32, B): s-chunks of 64, 4-way unroll.
// ---------------------------------------------------------------------------
__global__ __launch_bounds__(128) void wsum_kernel(const float* __restrict__ A,
                                                   const int* __restrict__ lengths) {
    int q = blockIdx.x, b = blockIdx.y;
    int tid = threadIdx.x;
    int len = lengths[b];
    int nv = len - q * 64;
    nv = (nv > 64) ? 64 : nv;

    float4 acc0 = make_float4(0.f, 0.f, 0.f, 0.f);
    float4 acc1 = make_float4(0.f, 0.f, 0.f, 0.f);
    if (nv > 0) {
        const float* Ab = A + ((size_t)b * S_ + q * 64) * E_ + tid * 4;
        const float* at = g_attn + (size_t)b * S_ + q * 64;
        int s = 0;
        for (; s + 4 <= nv; s += 4) {
            float w0 = at[s], w1 = at[s + 1], w2 = at[s + 2], w3 = at[s + 3];
            float4 a0 = *reinterpret_cast<const float4*>(Ab + (size_t)s * E_);
            float4 a1 = *reinterpret_cast<const float4*>(Ab + (size_t)(s + 1) * E_);
            float4 a2 = *reinterpret_cast<const float4*>(Ab + (size_t)(s + 2) * E_);
            float4 a3 = *reinterpret_cast<const float4*>(Ab + (size_t)(s + 3) * E_);
            acc0.x += w0 * a0.x + w2 * a2.x;
            acc0.y += w0 * a0.y + w2 * a2.y;
            acc0.z += w0 * a0.z + w2 * a2.z;
            acc0.w += w0 * a0.w + w2 * a2.w;
            acc1.x += w1 * a1.x + w3 * a3.x;
            acc1.y += w1 * a1.y + w3 * a3.y;
            acc1.z += w1 * a1.z + w3 * a3.z;
            acc1.w += w1 * a1.w + w3 * a3.w;
        }
        for (; s < nv; s++) {
            float w = at[s];
            float4 a = *reinterpret_cast<const float4*>(Ab + (size_t)s * E_);
            acc0.x += w * a.x; acc0.y += w * a.y; acc0.z += w * a.z; acc0.w += w * a.w;
        }
    }
    acc0.x += acc1.x; acc0.y += acc1.y; acc0.z += acc1.z; acc0.w += acc1.w;
    *reinterpret_cast<float4*>(g_part + ((size_t)(q * B_ + b)) * E_ + tid * 4) = acc0;
}

// ---------------------------------------------------------------------------
// Kernel 5: reduce 32 partials -> attention_features
// ---------------------------------------------------------------------------
__global__ void reduce_kernel(float* __restrict__ feat) {
    int b = blockIdx.x, e = threadIdx.x;
    float s = 0.0f;
#pragma unroll
    for (int q = 0; q < 32; q++) s += g_part[((size_t)(q * B_ + b)) * E_ + e];
    feat[b * E_ + e] = s;
}

// ---------------------------------------------------------------------------
extern "C" void kernel_launch(void* const* d_in, const int* in_sizes, int n_in,
                              void* d_out, int out_size) {
    const float* A        = (const float*)d_in[0];
    const int*   lengths  = (const int*)d_in[1];
    const float* context  = (const float*)d_in[2];
    const float* W_word   = (const float*)d_in[3];
    const float* b_word   = (const float*)d_in[4];
    const float* W_ctx    = (const float*)d_in[5];
    const float* b_ctx    = (const float*)d_in[6];
    const float* w_hidden = (const float*)d_in[7];

    float* out = (float*)d_out;
    float* feat_out = out;
    float* attn_out = (out_size >= B_ * E_ + B_ * S_) ? out + B_ * E_ : nullptr;

    // smem: max(tiles 61440B, epilogue 128*132*4=67584B) + ctx/wh 2048B
    const int SCORES_SMEM = 128 * LDWF * 4 + 2048;  // 69632
    cudaFuncSetAttribute(scores_kernel, cudaFuncAttributeMaxDynamicSharedMemorySize,
                         SCORES_SMEM);

    ctx_kernel<<<B_, H_>>>(context, W_ctx, b_ctx, b_word);

    dim3 g2(S_ / 128, B_);
    scores_kernel<<<g2, 512, SCORES_SMEM>>>(A, W_word, lengths, w_hidden);

    attn_softmax_kernel<<<B_, 256>>>(lengths, attn_out);

    dim3 g4(32, B_);
    wsum_kernel<<<g4, 128>>>(A, lengths);

    reduce_kernel<<<B_, E_>>>(feat_out);
}

// round 15
// speedup vs baseline: 1.0020x; 1.0020x over previous
#include <cuda_runtime.h>
#include <cuda_fp16.h>
#include <mma.h>
#include <cstdint>
#include <cstddef>

using namespace nvcuda;

#define B_ 64
#define S_ 2048
#define E_ 512
#define C_ 512
#define H_ 256

// ---------------- scratch (static device globals; no allocation) ----------------
__device__ float g_ctx[B_ * H_];         // ctx_feat + b_ctx + b_word  [B,H]
__device__ float g_scores[B_ * S_];      // pre-softmax scores         [B,S]
__device__ float g_attn[B_ * S_];        // normalized attention       [B,S]
__device__ float g_part[32 * B_ * E_];   // weighted-sum partials      [32,B,E]
__device__ unsigned g_ticket;            // persistent-CTA work queue

// ---------------------------------------------------------------------------
// ticket reset (runs before scores every launch; graph-capturable)
// ---------------------------------------------------------------------------
__global__ void reset_ticket_kernel() { g_ticket = 0u; }

// ---------------------------------------------------------------------------
// Kernel 1: ctx_feat[b,h] = b_ctx[h] + b_word[h] + context[b,:] . W_ctx[h,:]
// grid (B, 2) x 128 threads for 2x parallelism vs single-block-per-b.
// ---------------------------------------------------------------------------
__global__ __launch_bounds__(128) void ctx_kernel(const float* __restrict__ context,
                                                  const float* __restrict__ W_ctx,
                                                  const float* __restrict__ b_ctx,
                                                  const float* __restrict__ b_word) {
    int b = blockIdx.x;
    int h = blockIdx.y * 128 + threadIdx.x;
    const float4* wr = reinterpret_cast<const float4*>(W_ctx + (size_t)h * C_);
    const float4* cr = reinterpret_cast<const float4*>(context + (size_t)b * C_);
    float acc = b_ctx[h] + b_word[h];
#pragma unroll 8
    for (int i = 0; i < C_ / 4; i++) {
        float4 w = wr[i];
        float4 c = cr[i];
        acc += w.x * c.x + w.y * c.y + w.z * c.z + w.w * c.w;
    }
    g_ctx[b * H_ + h] = acc;
}

// ---------------------------------------------------------------------------
// Kernel 2: scores = w_hidden . tanh(A@W_word^T + ctx), fp16 wmma m16n16k16,
// persistent CTAs with an atomic ticket queue (balances length-skewed tiles).
// Tile = 128 s-rows x 256 H-cols x K=512; 512 threads (16 warps, wm0..3 x wn0..3).
// Register-prefetched LDG -> cvt.f16 -> STS double-buffered K=32 chunks.
// ---------------------------------------------------------------------------
#define LDH 40                 // smem leading dim in halves (80B, 16B multiple)
#define A_HL (128 * LDH)       // halves per A buffer
#define B_HL (256 * LDH)       // halves per B buffer
#define LDWF 132
#define N_TILES 1024           // 16 s-tiles x 64 batches

__global__ __launch_bounds__(512, 1) void scores_kernel(
    const float* __restrict__ A,         // [B,S,E]
    const float* __restrict__ Ww,        // W_word [H,E]
    const int* __restrict__ lengths,
    const float* __restrict__ w_hidden) {
    extern __shared__ __align__(128) char smc[];
    __half* As0 = reinterpret_cast<__half*>(smc);                 // [2][A_HL]
    __half* Bs0 = reinterpret_cast<__half*>(smc + 2 * A_HL * 2);  // [2][B_HL]
    float* epif = reinterpret_cast<float*>(smc);                  // epilogue 128xLDWF
    float* ctx_s = reinterpret_cast<float*>(smc + 128 * LDWF * 4);
    float* wh_s = ctx_s + 256;
    __shared__ unsigned s_tile;

    int tid = threadIdx.x;
    int lane = tid & 31, wid = tid >> 5;
    int wm = wid & 3, wn = wid >> 2;

    if (tid < 256) wh_s[tid] = w_hidden[tid];  // loop-invariant

    // per-thread staging slots (K=32 chunk): A 2 x float4, B 4 x float4
    int ar[2], ac[2], br[4], bc[4];
#pragma unroll
    for (int i = 0; i < 2; i++) {
        int idx = tid + i * 512;
        ar[i] = idx >> 3;
        ac[i] = (idx & 7) * 4;
    }
#pragma unroll
    for (int i = 0; i < 4; i++) {
        int idx = tid + i * 512;
        br[i] = idx >> 3;
        bc[i] = (idx & 7) * 4;
    }

    for (;;) {
        if (tid == 0) s_tile = atomicAdd(&g_ticket, 1u);
        __syncthreads();
        unsigned t = s_tile;
        if (t >= N_TILES) break;
        int b = (int)(t >> 4);
        int s0 = (int)(t & 15u) * 128;
        int len = lengths[b];
        if (s0 < len) {
            if (tid < 256) ctx_s[tid] = g_ctx[b * H_ + tid];

            wmma::fragment<wmma::accumulator, 16, 16, 16, float> acc[2][4];
#pragma unroll
            for (int mi = 0; mi < 2; mi++)
#pragma unroll
                for (int ni = 0; ni < 4; ni++) wmma::fill_fragment(acc[mi][ni], 0.0f);

            const float* Ab = A + ((size_t)b * S_ + s0) * E_;

            float4 ra[2], rb[4];
#pragma unroll
            for (int i = 0; i < 2; i++)
                ra[i] = *reinterpret_cast<const float4*>(Ab + (size_t)ar[i] * E_ + ac[i]);
#pragma unroll
            for (int i = 0; i < 4; i++)
                rb[i] = *reinterpret_cast<const float4*>(Ww + (size_t)br[i] * E_ + bc[i]);

            for (int kc = 0; kc < 16; kc++) {
                int buf = kc & 1;
                __half* Asb = As0 + buf * A_HL;
                __half* Bsb = Bs0 + buf * B_HL;
#pragma unroll
                for (int i = 0; i < 2; i++) {
                    __half2 p0 = __floats2half2_rn(ra[i].x, ra[i].y);
                    __half2 p1 = __floats2half2_rn(ra[i].z, ra[i].w);
                    uint2 u = make_uint2(*reinterpret_cast<uint32_t*>(&p0),
                                         *reinterpret_cast<uint32_t*>(&p1));
                    *reinterpret_cast<uint2*>(&Asb[ar[i] * LDH + ac[i]]) = u;
                }
#pragma unroll
                for (int i = 0; i < 4; i++) {
                    __half2 p0 = __floats2half2_rn(rb[i].x, rb[i].y);
                    __half2 p1 = __floats2half2_rn(rb[i].z, rb[i].w);
                    uint2 u = make_uint2(*reinterpret_cast<uint32_t*>(&p0),
                                         *reinterpret_cast<uint32_t*>(&p1));
                    *reinterpret_cast<uint2*>(&Bsb[br[i] * LDH + bc[i]]) = u;
                }
                __syncthreads();
                if (kc + 1 < 16) {  // prefetch next chunk; latency hides under mma
                    int k0 = (kc + 1) * 32;
#pragma unroll
                    for (int i = 0; i < 2; i++)
                        ra[i] = *reinterpret_cast<const float4*>(Ab + (size_t)ar[i] * E_ +
                                                                 k0 + ac[i]);
#pragma unroll
                    for (int i = 0; i < 4; i++)
                        rb[i] = *reinterpret_cast<const float4*>(Ww + (size_t)br[i] * E_ +
                                                                 k0 + bc[i]);
                }
                const __half* As = As0 + buf * A_HL;
                const __half* Bs = Bs0 + buf * B_HL;
#pragma unroll
                for (int kk = 0; kk < 2; kk++) {
                    int ko = kk * 16;
                    wmma::fragment<wmma::matrix_a, 16, 16, 16, __half, wmma::row_major> af[2];
                    wmma::load_matrix_sync(af[0], As + (wm * 32) * LDH + ko, LDH);
                    wmma::load_matrix_sync(af[1], As + (wm * 32 + 16) * LDH + ko, LDH);
#pragma unroll
                    for (int ni = 0; ni < 4; ni++) {
                        wmma::fragment<wmma::matrix_b, 16, 16, 16, __half, wmma::col_major> bf;
                        wmma::load_matrix_sync(bf, Bs + (wn * 64 + ni * 16) * LDH + ko, LDH);
                        wmma::mma_sync(acc[0][ni], af[0], bf, acc[0][ni]);
                        wmma::mma_sync(acc[1][ni], af[1], bf, acc[1][ni]);
                    }
                }
                // next iteration writes buf^1, already drained before the sync above
            }

            // ---- epilogue: two column-halves via smem, tanh.approx + dot ----
            float psum[8];
#pragma unroll
            for (int rr = 0; rr < 8; rr++) psum[rr] = 0.0f;

#pragma unroll
            for (int hh = 0; hh < 2; hh++) {
                __syncthreads();
                if ((wn >> 1) == hh) {
                    int cw = (wn & 1) * 64;
#pragma unroll
                    for (int mi = 0; mi < 2; mi++)
#pragma unroll
                        for (int ni = 0; ni < 4; ni++)
                            wmma::store_matrix_sync(
                                epif + (wm * 32 + mi * 16) * LDWF + cw + ni * 16,
                                acc[mi][ni], LDWF, wmma::mem_row_major);
                }
                __syncthreads();
#pragma unroll
                for (int rr = 0; rr < 8; rr++) {
                    int r = wid * 8 + rr;
#pragma unroll
                    for (int j = 0; j < 4; j++) {
                        int c = lane + j * 32;
                        float x = epif[r * LDWF + c] + ctx_s[hh * 128 + c];
                        float th;
                        asm("tanh.approx.f32 %0, %1;" : "=f"(th) : "f"(x));
                        psum[rr] += th * wh_s[hh * 128 + c];
                    }
                }
            }
#pragma unroll
            for (int rr = 0; rr < 8; rr++) {
                float s = psum[rr];
#pragma unroll
                for (int o = 16; o > 0; o >>= 1) s += __shfl_xor_sync(0xffffffffu, s, o);
                if (lane == 0) g_scores[(size_t)b * S_ + s0 + wid * 8 + rr] = s;
            }
        }
        __syncthreads();  // all reads of s_tile/smem done before next ticket overwrite
    }
}

// ---------------------------------------------------------------------------
// Kernel 3: masked softmax (exact: exp(s-m)/L on valid prefix), 512 threads
// ---------------------------------------------------------------------------
__global__ __launch_bounds__(512) void attn_softmax_kernel(const int* __restrict__ lengths,
                                                           float* __restrict__ attn_out) {
    int b = blockIdx.x, tid = threadIdx.x;
    int lane = tid & 31, wid = tid >> 5;
    int len = lengths[b];
    const float* sc = g_scores + (size_t)b * S_;

    float v[4];
    float m = -1e30f;
#pragma unroll
    for (int i = 0; i < 4; i++) {
        int s = tid + i * 512;
        v[i] = (s < len) ? sc[s] : -1e30f;
        m = fmaxf(m, v[i]);
    }
#pragma unroll
    for (int o = 16; o > 0; o >>= 1) m = fmaxf(m, __shfl_xor_sync(0xffffffffu, m, o));
    __shared__ float red[16];
    if (lane == 0) red[wid] = m;
    __syncthreads();
    float mm = red[0];
#pragma unroll
    for (int i = 1; i < 16; i++) mm = fmaxf(mm, red[i]);

    float t[4];
    float L = 0.0f;
#pragma unroll
    for (int i = 0; i < 4; i++) {
        int s = tid + i * 512;
        t[i] = (s < len) ? __expf(v[i] - mm) : 0.0f;
        L += t[i];
    }
#pragma unroll
    for (int o = 16; o > 0; o >>= 1) L += __shfl_xor_sync(0xffffffffu, L, o);
    __syncthreads();
    if (lane == 0) red[wid] = L;
    __syncthreads();
    float Lt = 0.0f;
#pragma unroll
    for (int i = 0; i < 16; i++) Lt += red[i];
    float inv = __fdividef(1.0f, Lt);

#pragma unroll
    for (int i = 0; i < 4; i++) {
        int s = tid + i * 512;
        float a = t[i] * inv;
        g_attn[(size_t)b * S_ + s] = a;
        if (attn_out) attn_out[(size_t)b * S_ + s] = a;
    }
}

// ---------------------------------------------------------------------------
// Kernel 4: weighted-sum partials. grid (32, B): s-chunks of 64, 8-way unroll
// with 4 accumulator chains (MLP 32 loads/warp in flight).
// ---------------------------------------------------------------------------
__global__ __launch_bounds__(128) void wsum_kernel(const float* __restrict__ A,
                                                   const int* __restrict__ lengths) {
    int q = blockIdx.x, b = blockIdx.y;
    int tid = threadIdx.x;
    int len = lengths[b];
    int nv = len - q * 64;
    nv = (nv > 64) ? 64 : nv;

    float4 k0 = make_float4(0.f, 0.f, 0.f, 0.f);
    float4 k1 = k0, k2 = k0, k3 = k0;
    if (nv > 0) {
        const float* Ab = A + ((size_t)b * S_ + q * 64) * E_ + tid * 4;
        const float* at = g_attn + (size_t)b * S_ + q * 64;
        int s = 0;
        for (; s + 8 <= nv; s += 8) {
            float w0 = at[s], w1 = at[s + 1], w2 = at[s + 2], w3 = at[s + 3];
            float w4 = at[s + 4], w5 = at[s + 5], w6 = at[s + 6], w7 = at[s + 7];
            float4 a0 = *reinterpret_cast<const float4*>(Ab + (size_t)(s + 0) * E_);
            float4 a1 = *reinterpret_cast<const float4*>(Ab + (size_t)(s + 1) * E_);
            float4 a2 = *reinterpret_cast<const float4*>(Ab + (size_t)(s + 2) * E_);
            float4 a3 = *reinterpret_cast<const float4*>(Ab + (size_t)(s + 3) * E_);
            float4 a4 = *reinterpret_cast<const float4*>(Ab + (size_t)(s + 4) * E_);
            float4 a5 = *reinterpret_cast<const float4*>(Ab + (size_t)(s + 5) * E_);
            float4 a6 = *reinterpret_cast<const float4*>(Ab + (size_t)(s + 6) * E_);
            float4 a7 = *reinterpret_cast<const float4*>(Ab + (size_t)(s + 7) * E_);
            k0.x += w0 * a0.x + w4 * a4.x; k0.y += w0 * a0.y + w4 * a4.y;
            k0.z += w0 * a0.z + w4 * a4.z; k0.w += w0 * a0.w + w4 * a4.w;
            k1.x += w1 * a1.x + w5 * a5.x; k1.y += w1 * a1.y + w5 * a5.y;
            k1.z += w1 * a1.z + w5 * a5.z; k1.w += w1 * a1.w + w5 * a5.w;
            k2.x += w2 * a2.x + w6 * a6.x; k2.y += w2 * a2.y + w6 * a6.y;
            k2.z += w2 * a2.z + w6 * a6.z; k2.w += w2 * a2.w + w6 * a6.w;
            k3.x += w3 * a3.x + w7 * a7.x; k3.y += w3 * a3.y + w7 * a7.y;
            k3.z += w3 * a3.z + w7 * a7.z; k3.w += w3 * a3.w + w7 * a7.w;
        }
        for (; s < nv; s++) {
            float w = at[s];
            float4 a = *reinterpret_cast<const float4*>(Ab + (size_t)s * E_);
            k0.x += w * a.x; k0.y += w * a.y; k0.z += w * a.z; k0.w += w * a.w;
        }
    }
    k0.x += k1.x + k2.x + k3.x;
    k0.y += k1.y + k2.y + k3.y;
    k0.z += k1.z + k2.z + k3.z;
    k0.w += k1.w + k2.w + k3.w;
    *reinterpret_cast<float4*>(g_part + ((size_t)(q * B_ + b)) * E_ + tid * 4) = k0;
}

// ---------------------------------------------------------------------------
// Kernel 5: reduce 32 partials -> attention_features
// ---------------------------------------------------------------------------
__global__ void reduce_kernel(float* __restrict__ feat) {
    int b = blockIdx.x, e = threadIdx.x;
    float s = 0.0f;
#pragma unroll
    for (int q = 0; q < 32; q++) s += g_part[((size_t)(q * B_ + b)) * E_ + e];
    feat[b * E_ + e] = s;
}

// ---------------------------------------------------------------------------
extern "C" void kernel_launch(void* const* d_in, const int* in_sizes, int n_in,
                              void* d_out, int out_size) {
    const float* A        = (const float*)d_in[0];
    const int*   lengths  = (const int*)d_in[1];
    const float* context  = (const float*)d_in[2];
    const float* W_word   = (const float*)d_in[3];
    const float* b_word   = (const float*)d_in[4];
    const float* W_ctx    = (const float*)d_in[5];
    const float* b_ctx    = (const float*)d_in[6];
    const float* w_hidden = (const float*)d_in[7];

    float* out = (float*)d_out;
    float* feat_out = out;
    float* attn_out = (out_size >= B_ * E_ + B_ * S_) ? out + B_ * E_ : nullptr;

    const int SCORES_SMEM = 128 * LDWF * 4 + 2048;  // 69632
    cudaFuncSetAttribute(scores_kernel, cudaFuncAttributeMaxDynamicSharedMemorySize,
                         SCORES_SMEM);

    reset_ticket_kernel<<<1, 1>>>();

    dim3 gc(B_, 2);
    ctx_kernel<<<gc, 128>>>(context, W_ctx, b_ctx, b_word);

    scores_kernel<<<160, 512, SCORES_SMEM>>>(A, W_word, lengths, w_hidden);  // ~1/SM (152 SMs)

    attn_softmax_kernel<<<B_, 512>>>(lengths, attn_out);

    dim3 g4(32, B_);
    wsum_kernel<<<g4, 128>>>(A, lengths);

    reduce_kernel<<<B_, E_>>>(feat_out);
}

// round 16
// speedup vs baseline: 1.1235x; 1.1213x over previous
#include <cuda_runtime.h>
#include <cuda_fp16.h>
#include <mma.h>
#include <cstdint>
#include <cstddef>

using namespace nvcuda;

#define B_ 64
#define S_ 2048
#define E_ 512
#define C_ 512
#define H_ 256

// ---------------- scratch (static device globals; no allocation) ----------------
__device__ float g_ctx[B_ * H_];             // ctx_feat + b_ctx + b_word  [B,H]
__device__ float g_scores[B_ * S_];          // pre-softmax scores         [B,S]
__device__ float4 g_tpart4[B_ * 16 * 128];   // per-tile weighted partials [B,16,E/4]
__device__ float g_mt[B_ * 16];              // per-tile score max
__device__ float g_lt[B_ * 16];              // per-tile exp-sum
__device__ unsigned g_ticket;                // persistent-CTA work queue
__device__ unsigned g_ctx_done;              // 32 when all ctx tickets finished

// ---------------------------------------------------------------------------
// counters reset (graph-capturable, runs first every launch)
// ---------------------------------------------------------------------------
__global__ void reset_kernel() {
    g_ticket = 0u;
    g_ctx_done = 0u;
}

// ---------------------------------------------------------------------------
// Mega kernel: persistent CTAs over tickets.
//   tickets [0,32):        ctx slices  (g_ctx[b,h] = b_ctx+b_word+ctx.Wctx row)
//   tickets [32,1056):     score tiles: fp16 wmma GEMM (128x256xK512) ->
//                          tanh.approx -> dot(w_hidden) -> scores, then
//                          tile-softmax partials: m_t, L_t, sum exp(s-m_t)*A[r,:]
//                          (A rows re-read from hot L2, hidden under other CTAs'
//                          tensor work).
// ---------------------------------------------------------------------------
#define LDH 40                 // smem leading dim in halves (80B, 16B multiple)
#define A_HL (128 * LDH)
#define B_HL (256 * LDH)
#define LDWF 132
#define N_CTX_T 32u
#define N_TILE_T 1024u
#define N_TICKETS (N_CTX_T + N_TILE_T)

__global__ __launch_bounds__(512, 1) void mega_kernel(
    const float* __restrict__ A,         // [B,S,E]
    const float* __restrict__ Ww,        // W_word [H,E]
    const int* __restrict__ lengths,
    const float* __restrict__ w_hidden,
    const float* __restrict__ context,   // [B,C]
    const float* __restrict__ W_ctx,     // [H,C]
    const float* __restrict__ b_ctx,
    const float* __restrict__ b_word) {
    extern __shared__ __align__(128) char smc[];
    __half* As0 = reinterpret_cast<__half*>(smc);                 // [2][A_HL]
    __half* Bs0 = reinterpret_cast<__half*>(smc + 2 * A_HL * 2);  // [2][B_HL]
    float* epif = reinterpret_cast<float*>(smc);                  // epilogue 128xLDWF
    float* ctx_s = reinterpret_cast<float*>(smc + 128 * LDWF * 4);
    float* wh_s = ctx_s + 256;
    __shared__ unsigned s_tile;
    __shared__ float row_sc[128];  // tile row scores
    __shared__ float wrow[128];    // tile softmax weights
    __shared__ float s_aux;        // m_t broadcast

    int tid = threadIdx.x;
    int lane = tid & 31, wid = tid >> 5;
    int wm = wid & 3, wn = wid >> 2;

    if (tid < 256) wh_s[tid] = w_hidden[tid];  // loop-invariant

    // per-thread staging slots (K=32 chunk): A 2 x float4, B 4 x float4
    int ar[2], ac[2], br[4], bc[4];
#pragma unroll
    for (int i = 0; i < 2; i++) {
        int idx = tid + i * 512;
        ar[i] = idx >> 3;
        ac[i] = (idx & 7) * 4;
    }
#pragma unroll
    for (int i = 0; i < 4; i++) {
        int idx = tid + i * 512;
        br[i] = idx >> 3;
        bc[i] = (idx & 7) * 4;
    }

    for (;;) {
        if (tid == 0) s_tile = atomicAdd(&g_ticket, 1u);
        __syncthreads();
        unsigned t = s_tile;
        if (t >= N_TICKETS) break;

        if (t < N_CTX_T) {
            // ---------------- ctx ticket: 512 h-dot-products ----------------
            int idx = (int)t * 512 + tid;
            int cb = idx >> 8, h = idx & 255;
            const float4* wr = reinterpret_cast<const float4*>(W_ctx + (size_t)h * C_);
            const float4* cr = reinterpret_cast<const float4*>(context + (size_t)cb * C_);
            float acc = b_ctx[h] + b_word[h];
#pragma unroll 8
            for (int i = 0; i < C_ / 4; i++) {
                float4 w = wr[i];
                float4 c = cr[i];
                acc += w.x * c.x + w.y * c.y + w.z * c.z + w.w * c.w;
            }
            g_ctx[cb * H_ + h] = acc;
            __threadfence();
            __syncthreads();
            if (tid == 0) atomicAdd(&g_ctx_done, 1u);
        } else {
            // ---------------- score tile ----------------
            unsigned st = t - N_CTX_T;
            int b = (int)(st >> 4);
            int tile = (int)(st & 15u);
            int s0 = tile * 128;
            int len = lengths[b];
            if (s0 < len) {
                int nv = len - s0;
                nv = (nv > 128) ? 128 : nv;

                wmma::fragment<wmma::accumulator, 16, 16, 16, float> acc[2][4];
#pragma unroll
                for (int mi = 0; mi < 2; mi++)
#pragma unroll
                    for (int ni = 0; ni < 4; ni++) wmma::fill_fragment(acc[mi][ni], 0.0f);

                const float* Ab = A + ((size_t)b * S_ + s0) * E_;

                float4 ra[2], rb[4];
#pragma unroll
                for (int i = 0; i < 2; i++)
                    ra[i] = *reinterpret_cast<const float4*>(Ab + (size_t)ar[i] * E_ + ac[i]);
#pragma unroll
                for (int i = 0; i < 4; i++)
                    rb[i] = *reinterpret_cast<const float4*>(Ww + (size_t)br[i] * E_ + bc[i]);

                for (int kc = 0; kc < 16; kc++) {
                    int buf = kc & 1;
                    __half* Asb = As0 + buf * A_HL;
                    __half* Bsb = Bs0 + buf * B_HL;
#pragma unroll
                    for (int i = 0; i < 2; i++) {
                        __half2 p0 = __floats2half2_rn(ra[i].x, ra[i].y);
                        __half2 p1 = __floats2half2_rn(ra[i].z, ra[i].w);
                        uint2 u = make_uint2(*reinterpret_cast<uint32_t*>(&p0),
                                             *reinterpret_cast<uint32_t*>(&p1));
                        *reinterpret_cast<uint2*>(&Asb[ar[i] * LDH + ac[i]]) = u;
                    }
#pragma unroll
                    for (int i = 0; i < 4; i++) {
                        __half2 p0 = __floats2half2_rn(rb[i].x, rb[i].y);
                        __half2 p1 = __floats2half2_rn(rb[i].z, rb[i].w);
                        uint2 u = make_uint2(*reinterpret_cast<uint32_t*>(&p0),
                                             *reinterpret_cast<uint32_t*>(&p1));
                        *reinterpret_cast<uint2*>(&Bsb[br[i] * LDH + bc[i]]) = u;
                    }
                    __syncthreads();
                    if (kc + 1 < 16) {  // prefetch next chunk, hides under mma
                        int k0 = (kc + 1) * 32;
#pragma unroll
                        for (int i = 0; i < 2; i++)
                            ra[i] = *reinterpret_cast<const float4*>(Ab + (size_t)ar[i] * E_ +
                                                                     k0 + ac[i]);
#pragma unroll
                        for (int i = 0; i < 4; i++)
                            rb[i] = *reinterpret_cast<const float4*>(Ww + (size_t)br[i] * E_ +
                                                                     k0 + bc[i]);
                    }
                    const __half* As = As0 + buf * A_HL;
                    const __half* Bs = Bs0 + buf * B_HL;
#pragma unroll
                    for (int kk = 0; kk < 2; kk++) {
                        int ko = kk * 16;
                        wmma::fragment<wmma::matrix_a, 16, 16, 16, __half, wmma::row_major> af[2];
                        wmma::load_matrix_sync(af[0], As + (wm * 32) * LDH + ko, LDH);
                        wmma::load_matrix_sync(af[1], As + (wm * 32 + 16) * LDH + ko, LDH);
#pragma unroll
                        for (int ni = 0; ni < 4; ni++) {
                            wmma::fragment<wmma::matrix_b, 16, 16, 16, __half,
                                           wmma::col_major> bf;
                            wmma::load_matrix_sync(bf, Bs + (wn * 64 + ni * 16) * LDH + ko, LDH);
                            wmma::mma_sync(acc[0][ni], af[0], bf, acc[0][ni]);
                            wmma::mma_sync(acc[1][ni], af[1], bf, acc[1][ni]);
                        }
                    }
                }

                // ---- wait for ctx (long done by now), stage it ----
                if (tid == 0) {
                    while (atomicAdd(&g_ctx_done, 0u) < N_CTX_T) {}
                    __threadfence();
                }
                __syncthreads();
                if (tid < 256) ctx_s[tid] = g_ctx[b * H_ + tid];

                // ---- epilogue: tanh.approx + dot(w_hidden) -> row scores ----
                float psum[8];
#pragma unroll
                for (int rr = 0; rr < 8; rr++) psum[rr] = 0.0f;

#pragma unroll
                for (int hh = 0; hh < 2; hh++) {
                    __syncthreads();
                    if ((wn >> 1) == hh) {
                        int cw = (wn & 1) * 64;
#pragma unroll
                        for (int mi = 0; mi < 2; mi++)
#pragma unroll
                            for (int ni = 0; ni < 4; ni++)
                                wmma::store_matrix_sync(
                                    epif + (wm * 32 + mi * 16) * LDWF + cw + ni * 16,
                                    acc[mi][ni], LDWF, wmma::mem_row_major);
                    }
                    __syncthreads();
#pragma unroll
                    for (int rr = 0; rr < 8; rr++) {
                        int r = wid * 8 + rr;
#pragma unroll
                        for (int j = 0; j < 4; j++) {
                            int c = lane + j * 32;
                            float x = epif[r * LDWF + c] + ctx_s[hh * 128 + c];
                            float th;
                            asm("tanh.approx.f32 %0, %1;" : "=f"(th) : "f"(x));
                            psum[rr] += th * wh_s[hh * 128 + c];
                        }
                    }
                }
#pragma unroll
                for (int rr = 0; rr < 8; rr++) {
                    float s = psum[rr];
#pragma unroll
                    for (int o = 16; o > 0; o >>= 1) s += __shfl_xor_sync(0xffffffffu, s, o);
                    if (lane == 0) {
                        int r = wid * 8 + rr;
                        g_scores[(size_t)b * S_ + s0 + r] = s;
                        row_sc[r] = s;
                    }
                }
                __syncthreads();

                // ---- tile softmax stats: m_t, weights, L_t ----
                if (wid == 0) {
                    float m = -1e30f;
#pragma unroll
                    for (int k = 0; k < 4; k++) {
                        int r = lane + k * 32;
                        float v = (r < nv) ? row_sc[r] : -1e30f;
                        m = fmaxf(m, v);
                    }
#pragma unroll
                    for (int o = 16; o > 0; o >>= 1)
                        m = fmaxf(m, __shfl_xor_sync(0xffffffffu, m, o));
                    if (lane == 0) s_aux = m;
                }
                __syncthreads();
                float mt = s_aux;
                if (tid < 128) wrow[tid] = (tid < nv) ? __expf(row_sc[tid] - mt) : 0.0f;
                __syncthreads();
                if (wid == 0) {
                    float L = 0.0f;
#pragma unroll
                    for (int k = 0; k < 4; k++) L += wrow[lane + k * 32];
#pragma unroll
                    for (int o = 16; o > 0; o >>= 1) L += __shfl_xor_sync(0xffffffffu, L, o);
                    if (lane == 0) {
                        g_mt[b * 16 + tile] = mt;
                        g_lt[b * 16 + tile] = L;
                    }
                }

                // ---- tile weighted partial: sum_r w_r * A[r,:], A from hot L2 ----
                {
                    int e4 = tid & 127, sg = tid >> 7;  // 4 row-groups x 128 cols
                    const float* Abase = Ab + e4 * 4;
                    float4 pacc = make_float4(0.f, 0.f, 0.f, 0.f);
#pragma unroll 4
                    for (int r = sg; r < nv; r += 4) {
                        float w = wrow[r];
                        float4 a = *reinterpret_cast<const float4*>(Abase + (size_t)r * E_);
                        pacc.x += w * a.x;
                        pacc.y += w * a.y;
                        pacc.z += w * a.z;
                        pacc.w += w * a.w;
                    }
                    float4* red4 = reinterpret_cast<float4*>(smc);  // 8KB, GEMM bufs free
                    red4[sg * 128 + e4] = pacc;
                    __syncthreads();
                    if (sg == 0) {
                        float4 s0v = red4[e4];
                        float4 s1v = red4[128 + e4];
                        float4 s2v = red4[256 + e4];
                        float4 s3v = red4[384 + e4];
                        s0v.x += s1v.x + s2v.x + s3v.x;
                        s0v.y += s1v.y + s2v.y + s3v.y;
                        s0v.z += s1v.z + s2v.z + s3v.z;
                        s0v.w += s1v.w + s2v.w + s3v.w;
                        g_tpart4[(size_t)(b * 16 + tile) * 128 + e4] = s0v;
                    }
                }
            }
        }
        __syncthreads();  // smem quiesced before next ticket
    }
}

// ---------------------------------------------------------------------------
// Finalize: per batch combine tile partials; write feat and attn.
//   M = max m_t; L = sum e^{m_t-M} L_t; feat = sum e^{m_t-M} part_t / L;
//   attn_s = e^{sc_s - M}/L (valid), 0 (masked).
// ---------------------------------------------------------------------------
__global__ __launch_bounds__(512) void finalize_kernel(const int* __restrict__ lengths,
                                                       float* __restrict__ feat,
                                                       float* __restrict__ attn_out) {
    int b = blockIdx.x, tid = threadIdx.x;
    int len = lengths[b];
    int nt = (len + 127) >> 7;  // valid tiles, >= 1
    __shared__ float sM, sInv;
    __shared__ float sE[16];  // e^{m_t - M}

    if (tid < 32) {
        float m = (tid < nt) ? g_mt[b * 16 + tid] : -1e30f;
#pragma unroll
        for (int o = 16; o > 0; o >>= 1) m = fmaxf(m, __shfl_xor_sync(0xffffffffu, m, o));
        if (tid == 0) sM = m;
    }
    __syncthreads();
    float M = sM;
    if (tid < 32) {
        float e = (tid < nt) ? __expf(g_mt[b * 16 + tid] - M) : 0.0f;
        if (tid < 16) sE[tid] = e;
        float l = (tid < nt) ? e * g_lt[b * 16 + tid] : 0.0f;
#pragma unroll
        for (int o = 16; o > 0; o >>= 1) l += __shfl_xor_sync(0xffffffffu, l, o);
        if (tid == 0) sInv = __fdividef(1.0f, l);  // 1e-10 term <= 1e-10 relative
    }
    __syncthreads();
    float inv = sInv;

    // feat: E=512 columns, one per thread
    const float* gp = reinterpret_cast<const float*>(g_tpart4);
    float f = 0.0f;
    for (int t = 0; t < nt; t++)
        f += sE[t] * gp[(size_t)(b * 16 + t) * E_ + tid];
    feat[b * E_ + tid] = f * inv;

    // attn output
    if (attn_out) {
        const float* sc = g_scores + (size_t)b * S_;
#pragma unroll
        for (int i = 0; i < 4; i++) {
            int s = tid + i * 512;
            attn_out[(size_t)b * S_ + s] = (s < len) ? __expf(sc[s] - M) * inv : 0.0f;
        }
    }
}

// ---------------------------------------------------------------------------
extern "C" void kernel_launch(void* const* d_in, const int* in_sizes, int n_in,
                              void* d_out, int out_size) {
    const float* A        = (const float*)d_in[0];
    const int*   lengths  = (const int*)d_in[1];
    const float* context  = (const float*)d_in[2];
    const float* W_word   = (const float*)d_in[3];
    const float* b_word   = (const float*)d_in[4];
    const float* W_ctx    = (const float*)d_in[5];
    const float* b_ctx    = (const float*)d_in[6];
    const float* w_hidden = (const float*)d_in[7];

    float* out = (float*)d_out;
    float* feat_out = out;
    float* attn_out = (out_size >= B_ * E_ + B_ * S_) ? out + B_ * E_ : nullptr;

    const int SCORES_SMEM = 128 * LDWF * 4 + 2048;  // 69632
    cudaFuncSetAttribute(mega_kernel, cudaFuncAttributeMaxDynamicSharedMemorySize,
                         SCORES_SMEM);

    reset_kernel<<<1, 32>>>();
    mega_kernel<<<152, 512, SCORES_SMEM>>>(A, W_word, lengths, w_hidden,
                                           context, W_ctx, b_ctx, b_word);
    finalize_kernel<<<B_, 512>>>(lengths, feat_out, attn_out);
}